// round 2
// baseline (speedup 1.0000x reference)
#include <cuda_runtime.h>
#include <cuda_bf16.h>
#include <cstdint>

// Problem constants
#define NB    32
#define CIN   256
#define COUT  256
#define TT    128
#define VV    25
#define KK    3
#define KCOUT 768          // K*COUT
#define TVN   3200         // T*V
#define NTV   102400       // N*T*V
#define BN_EPS 1e-5f

// Scratch (device globals: allocation-free per harness rules)
__device__ float g_y1[(size_t)NB * KCOUT * TVN];   // [n][o][t][v]  314 MB
__device__ float g_y [(size_t)NB * COUT * TVN];    // [n][c][t][w]  105 MB
__device__ float g_sum[COUT];
__device__ float g_sqsum[COUT];

// ---------------------------------------------------------------------------
// Kernel 0: zero BN stat accumulators
// ---------------------------------------------------------------------------
__global__ void zero_stats_kernel() {
    int t = threadIdx.x;
    if (t < COUT) { g_sum[t] = 0.0f; g_sqsum[t] = 0.0f; }
}

// ---------------------------------------------------------------------------
// Kernel 1: y1[o, n*T*V] = W[o, ci] @ x[ci, n*T*V] + b[o]     (TF32 mma.sync)
//   M=768, N=102400, K=256.  Block tile 128x128, BK=32, 8 warps (4M x 2N),
//   warp tile 32x64 via m16n8k8 tf32.
// ---------------------------------------------------------------------------
__device__ __forceinline__ uint32_t f2tf(float f) {
    uint32_t r;
    asm("cvt.rna.tf32.f32 %0, %1;" : "=r"(r) : "f"(f));
    return r;
}

__device__ __forceinline__ void mma_tf32(float c[4], const uint32_t a[4], uint32_t b0, uint32_t b1) {
    asm volatile(
        "mma.sync.aligned.m16n8k8.row.col.f32.tf32.tf32.f32 "
        "{%0,%1,%2,%3}, {%4,%5,%6,%7}, {%8,%9}, {%0,%1,%2,%3};\n"
        : "+f"(c[0]), "+f"(c[1]), "+f"(c[2]), "+f"(c[3])
        : "r"(a[0]), "r"(a[1]), "r"(a[2]), "r"(a[3]), "r"(b0), "r"(b1));
}

#define LDA_S 36    // padded smem stride for A tile (conflict-free, 16B aligned)
#define LDB_S 136   // padded smem stride for B tile

__global__ __launch_bounds__(256) void gemm_kernel(
    const float* __restrict__ x, const float* __restrict__ W, const float* __restrict__ bias)
{
    __shared__ uint32_t As[128 * LDA_S];
    __shared__ uint32_t Bs[32 * LDB_S];

    const int m0     = blockIdx.x * 128;        // o tile (6 tiles)
    const int ct     = blockIdx.y;              // column tile (800 tiles)
    const int n      = ct / 25;
    const int tvbase = (ct % 25) * 128;

    const float* xB = x + (size_t)n * (CIN * TVN) + tvbase;  // B[ci][localcol] stride TVN

    const int tid  = threadIdx.x;
    const int lane = tid & 31;
    const int warp = tid >> 5;
    const int wm   = warp >> 1;   // 0..3  (M)
    const int wn   = warp & 1;    // 0..1  (N)
    const int g    = lane >> 2;
    const int k4   = lane & 3;

    float acc[2][8][4];
    #pragma unroll
    for (int i = 0; i < 2; i++)
        #pragma unroll
        for (int j = 0; j < 8; j++)
            #pragma unroll
            for (int r = 0; r < 4; r++) acc[i][j][r] = 0.0f;

    for (int kk = 0; kk < CIN; kk += 32) {
        // Load A tile: 128 rows x 32 cols of W
        {
            const int r  = tid >> 3;
            const int cv = (tid & 7) * 4;
            #pragma unroll
            for (int p = 0; p < 4; p++) {
                const int row = r + 32 * p;
                const float4 v = *(const float4*)(W + (size_t)(m0 + row) * CIN + kk + cv);
                uint32_t* d = &As[row * LDA_S + cv];
                d[0] = f2tf(v.x); d[1] = f2tf(v.y); d[2] = f2tf(v.z); d[3] = f2tf(v.w);
            }
        }
        // Load B tile: 32 rows (ci) x 128 cols
        {
            const int r  = tid >> 5;
            const int cv = (tid & 31) * 4;
            #pragma unroll
            for (int p = 0; p < 4; p++) {
                const int row = r + 8 * p;
                const float4 v = *(const float4*)(xB + (size_t)(kk + row) * TVN + cv);
                uint32_t* d = &Bs[row * LDB_S + cv];
                d[0] = f2tf(v.x); d[1] = f2tf(v.y); d[2] = f2tf(v.z); d[3] = f2tf(v.w);
            }
        }
        __syncthreads();

        #pragma unroll
        for (int k8 = 0; k8 < 4; k8++) {
            uint32_t a[2][4], b[8][2];
            #pragma unroll
            for (int i = 0; i < 2; i++) {
                const uint32_t* base = &As[(wm * 32 + i * 16 + g) * LDA_S + k8 * 8 + k4];
                a[i][0] = base[0];
                a[i][1] = base[8 * LDA_S];
                a[i][2] = base[4];
                a[i][3] = base[8 * LDA_S + 4];
            }
            #pragma unroll
            for (int j = 0; j < 8; j++) {
                const uint32_t* base = &Bs[(k8 * 8 + k4) * LDB_S + wn * 64 + j * 8 + g];
                b[j][0] = base[0];
                b[j][1] = base[4 * LDB_S];
            }
            #pragma unroll
            for (int i = 0; i < 2; i++)
                #pragma unroll
                for (int j = 0; j < 8; j++)
                    mma_tf32(acc[i][j], a[i], b[j][0], b[j][1]);
        }
        __syncthreads();
    }

    // Epilogue: +bias, store to g_y1[n][o][tv]
    float* yout = g_y1 + (size_t)n * (KCOUT * TVN) + tvbase;
    #pragma unroll
    for (int i = 0; i < 2; i++) {
        #pragma unroll
        for (int h = 0; h < 2; h++) {
            const int row = m0 + wm * 32 + i * 16 + g + h * 8;
            const float bv = bias[row];
            #pragma unroll
            for (int j = 0; j < 8; j++) {
                const int col = wn * 64 + j * 8 + k4 * 2;
                float2 val;
                val.x = acc[i][j][h * 2 + 0] + bv;
                val.y = acc[i][j][h * 2 + 1] + bv;
                *(float2*)(yout + (size_t)row * TVN + col) = val;
            }
        }
    }
}

// ---------------------------------------------------------------------------
// Kernel 2: y[n,c,t,w] = sum_{k,v} y1[n, k*COUT+c, t, v] * A[k,v,w]
//           + accumulate per-channel BN stats (sum, sumsq) via atomics.
//   Block = (c, n), 128 threads (one t each, 25 accumulators in registers).
// ---------------------------------------------------------------------------
__global__ __launch_bounds__(128) void contract_kernel(const float* __restrict__ A)
{
    __shared__ float As[KK][VV][28];   // padded rows: 112B -> 16B aligned, vec LDS
    __shared__ float red_s[4], red_s2[4];

    const int c = blockIdx.x;
    const int n = blockIdx.y;
    const int tid = threadIdx.x;   // == t (0..127)

    for (int i = tid; i < KK * VV * VV; i += 128) {
        int k = i / (VV * VV);
        int rem = i % (VV * VV);
        As[k][rem / VV][rem % VV] = A[i];
    }
    __syncthreads();

    const float* ybase = g_y1 + (size_t)n * (KCOUT * TVN) + (size_t)c * TVN + tid * VV;

    float acc[VV];
    #pragma unroll
    for (int w = 0; w < VV; w++) acc[w] = 0.0f;

    #pragma unroll
    for (int k = 0; k < KK; k++) {
        const float* yr = ybase + (size_t)k * (COUT * TVN);
        float vals[VV];
        #pragma unroll
        for (int v = 0; v < VV; v++) vals[v] = yr[v];
        #pragma unroll
        for (int v = 0; v < VV; v++) {
            const float val = vals[v];
            #pragma unroll
            for (int w = 0; w < VV; w++) acc[w] += val * As[k][v][w];
        }
    }

    float* out = g_y + ((size_t)n * COUT + c) * TVN + tid * VV;
    float s = 0.0f, s2 = 0.0f;
    #pragma unroll
    for (int w = 0; w < VV; w++) {
        out[w] = acc[w];
        s  += acc[w];
        s2 += acc[w] * acc[w];
    }

    // Block reduce then atomics
    #pragma unroll
    for (int off = 16; off > 0; off >>= 1) {
        s  += __shfl_down_sync(0xFFFFFFFFu, s,  off);
        s2 += __shfl_down_sync(0xFFFFFFFFu, s2, off);
    }
    const int lane = tid & 31, warp = tid >> 5;
    if (lane == 0) { red_s[warp] = s; red_s2[warp] = s2; }
    __syncthreads();
    if (tid == 0) {
        float S  = red_s[0]  + red_s[1]  + red_s[2]  + red_s[3];
        float S2 = red_s2[0] + red_s2[1] + red_s2[2] + red_s2[3];
        atomicAdd(&g_sum[c],   S);
        atomicAdd(&g_sqsum[c], S2);
    }
}

// ---------------------------------------------------------------------------
// Kernel 3: BN finalize + affine + ReLU (float4 elementwise)
// ---------------------------------------------------------------------------
__global__ __launch_bounds__(256) void bn_kernel(
    const float* __restrict__ gamma, const float* __restrict__ beta, float* __restrict__ out)
{
    const size_t i = (size_t)blockIdx.x * 256 + threadIdx.x;   // float4 index
    const int c = (int)((i * 4) / TVN) % COUT;                 // 4 | TVN -> uniform in vec

    const float cnt_inv = 1.0f / (float)NTV;
    const float mu  = g_sum[c] * cnt_inv;
    const float var = g_sqsum[c] * cnt_inv - mu * mu;
    const float inv = rsqrtf(var + BN_EPS);
    const float scale = gamma[c] * inv;
    const float shift = beta[c] - mu * scale;

    float4 v = ((const float4*)g_y)[i];
    v.x = fmaxf(v.x * scale + shift, 0.0f);
    v.y = fmaxf(v.y * scale + shift, 0.0f);
    v.z = fmaxf(v.z * scale + shift, 0.0f);
    v.w = fmaxf(v.w * scale + shift, 0.0f);
    ((float4*)out)[i] = v;
}

// ---------------------------------------------------------------------------
extern "C" void kernel_launch(void* const* d_in, const int* in_sizes, int n_in,
                              void* d_out, int out_size)
{
    const float* x     = (const float*)d_in[0];   // [32,256,128,25]
    const float* A     = (const float*)d_in[1];   // [3,25,25]
    const float* W     = (const float*)d_in[2];   // [768,256]
    const float* b     = (const float*)d_in[3];   // [768]
    const float* gamma = (const float*)d_in[4];   // [256]
    const float* beta  = (const float*)d_in[5];   // [256]

    zero_stats_kernel<<<1, 256>>>();

    dim3 g1(6, 800);
    gemm_kernel<<<g1, 256>>>(x, W, b);

    dim3 g2(COUT, NB);
    contract_kernel<<<g2, 128>>>(A);

    const int nvec = (NB * COUT * TVN) / 4;       // 6,553,600
    bn_kernel<<<nvec / 256, 256>>>(gamma, beta, (float*)d_out);
}

// round 3
// speedup vs baseline: 1.5488x; 1.5488x over previous
#include <cuda_runtime.h>
#include <cuda_bf16.h>
#include <cstdint>

// Problem constants
#define NB    32
#define CIN   256
#define COUT  256
#define TT    128
#define VV    25
#define KK    3
#define KCOUT 768          // K*COUT
#define TVN   3200         // T*V
#define NTV   102400       // N*T*V
#define BN_EPS 1e-5f

// Scratch (device globals: allocation-free per harness rules)
__device__ float g_y1[(size_t)NB * KCOUT * TVN];   // [n][o][t][v]  314 MB
__device__ float g_y [(size_t)NB * COUT * TVN];    // [n][c][t][w]  105 MB
__device__ float g_sum[COUT];
__device__ float g_sqsum[COUT];

// ---------------------------------------------------------------------------
// Kernel 0: zero BN stat accumulators
// ---------------------------------------------------------------------------
__global__ void zero_stats_kernel() {
    int t = threadIdx.x;
    if (t < COUT) { g_sum[t] = 0.0f; g_sqsum[t] = 0.0f; }
}

// ---------------------------------------------------------------------------
// Kernel 1: y1[o, n*T*V] = W[o, ci] @ x[ci, n*T*V] + b[o]     (TF32 mma.sync)
//   M=768, N=102400, K=256.  Block tile 128x128, BK=32, 8 warps (4M x 2N),
//   warp tile 32x64 via m16n8k8 tf32.
// ---------------------------------------------------------------------------
__device__ __forceinline__ uint32_t f2tf(float f) {
    uint32_t r;
    asm("cvt.rna.tf32.f32 %0, %1;" : "=r"(r) : "f"(f));
    return r;
}

__device__ __forceinline__ void mma_tf32(float c[4], const uint32_t a[4], uint32_t b0, uint32_t b1) {
    asm volatile(
        "mma.sync.aligned.m16n8k8.row.col.f32.tf32.tf32.f32 "
        "{%0,%1,%2,%3}, {%4,%5,%6,%7}, {%8,%9}, {%0,%1,%2,%3};\n"
        : "+f"(c[0]), "+f"(c[1]), "+f"(c[2]), "+f"(c[3])
        : "r"(a[0]), "r"(a[1]), "r"(a[2]), "r"(a[3]), "r"(b0), "r"(b1));
}

#define LDA_S 36    // padded smem stride for A tile (conflict-free, 16B aligned)
#define LDB_S 136   // padded smem stride for B tile

__global__ __launch_bounds__(256) void gemm_kernel(
    const float* __restrict__ x, const float* __restrict__ W, const float* __restrict__ bias)
{
    __shared__ uint32_t As[128 * LDA_S];
    __shared__ uint32_t Bs[32 * LDB_S];

    const int m0     = blockIdx.x * 128;        // o tile (6 tiles)
    const int ct     = blockIdx.y;              // column tile (800 tiles)
    const int n      = ct / 25;
    const int tvbase = (ct % 25) * 128;

    const float* xB = x + (size_t)n * (CIN * TVN) + tvbase;  // B[ci][localcol] stride TVN

    const int tid  = threadIdx.x;
    const int lane = tid & 31;
    const int warp = tid >> 5;
    const int wm   = warp >> 1;   // 0..3  (M)
    const int wn   = warp & 1;    // 0..1  (N)
    const int g    = lane >> 2;
    const int k4   = lane & 3;

    float acc[2][8][4];
    #pragma unroll
    for (int i = 0; i < 2; i++)
        #pragma unroll
        for (int j = 0; j < 8; j++)
            #pragma unroll
            for (int r = 0; r < 4; r++) acc[i][j][r] = 0.0f;

    for (int kk = 0; kk < CIN; kk += 32) {
        // Load A tile: 128 rows x 32 cols of W
        {
            const int r  = tid >> 3;
            const int cv = (tid & 7) * 4;
            #pragma unroll
            for (int p = 0; p < 4; p++) {
                const int row = r + 32 * p;
                const float4 v = *(const float4*)(W + (size_t)(m0 + row) * CIN + kk + cv);
                uint32_t* d = &As[row * LDA_S + cv];
                d[0] = f2tf(v.x); d[1] = f2tf(v.y); d[2] = f2tf(v.z); d[3] = f2tf(v.w);
            }
        }
        // Load B tile: 32 rows (ci) x 128 cols
        {
            const int r  = tid >> 5;
            const int cv = (tid & 31) * 4;
            #pragma unroll
            for (int p = 0; p < 4; p++) {
                const int row = r + 8 * p;
                const float4 v = *(const float4*)(xB + (size_t)(kk + row) * TVN + cv);
                uint32_t* d = &Bs[row * LDB_S + cv];
                d[0] = f2tf(v.x); d[1] = f2tf(v.y); d[2] = f2tf(v.z); d[3] = f2tf(v.w);
            }
        }
        __syncthreads();

        #pragma unroll
        for (int k8 = 0; k8 < 4; k8++) {
            uint32_t a[2][4], b[8][2];
            #pragma unroll
            for (int i = 0; i < 2; i++) {
                const uint32_t* base = &As[(wm * 32 + i * 16 + g) * LDA_S + k8 * 8 + k4];
                a[i][0] = base[0];
                a[i][1] = base[8 * LDA_S];
                a[i][2] = base[4];
                a[i][3] = base[8 * LDA_S + 4];
            }
            #pragma unroll
            for (int j = 0; j < 8; j++) {
                const uint32_t* base = &Bs[(k8 * 8 + k4) * LDB_S + wn * 64 + j * 8 + g];
                b[j][0] = base[0];
                b[j][1] = base[4 * LDB_S];
            }
            #pragma unroll
            for (int i = 0; i < 2; i++)
                #pragma unroll
                for (int j = 0; j < 8; j++)
                    mma_tf32(acc[i][j], a[i], b[j][0], b[j][1]);
        }
        __syncthreads();
    }

    // Epilogue: +bias, store to g_y1[n][o][tv]
    float* yout = g_y1 + (size_t)n * (KCOUT * TVN) + tvbase;
    #pragma unroll
    for (int i = 0; i < 2; i++) {
        #pragma unroll
        for (int h = 0; h < 2; h++) {
            const int row = m0 + wm * 32 + i * 16 + g + h * 8;
            const float bv = bias[row];
            #pragma unroll
            for (int j = 0; j < 8; j++) {
                const int col = wn * 64 + j * 8 + k4 * 2;
                float2 val;
                val.x = acc[i][j][h * 2 + 0] + bv;
                val.y = acc[i][j][h * 2 + 1] + bv;
                *(float2*)(yout + (size_t)row * TVN + col) = val;
            }
        }
    }
}

// ---------------------------------------------------------------------------
// Kernel 2: y[n,c,t,w] = sum_{k,v} y1[n, k*COUT+c, t, v] * A[k,v,w]
//           + accumulate per-channel BN stats (sum, sumsq) via atomics.
//   Block = (c, n), 128 threads (one t each, 25 accumulators in registers).
// ---------------------------------------------------------------------------
__global__ __launch_bounds__(128) void contract_kernel(const float* __restrict__ A)
{
    __shared__ float As[KK][VV][28];   // padded rows: 112B -> 16B aligned, vec LDS
    __shared__ float red_s[4], red_s2[4];

    const int c = blockIdx.x;
    const int n = blockIdx.y;
    const int tid = threadIdx.x;   // == t (0..127)

    for (int i = tid; i < KK * VV * VV; i += 128) {
        int k = i / (VV * VV);
        int rem = i % (VV * VV);
        As[k][rem / VV][rem % VV] = A[i];
    }
    __syncthreads();

    const float* ybase = g_y1 + (size_t)n * (KCOUT * TVN) + (size_t)c * TVN + tid * VV;

    float acc[VV];
    #pragma unroll
    for (int w = 0; w < VV; w++) acc[w] = 0.0f;

    #pragma unroll
    for (int k = 0; k < KK; k++) {
        const float* yr = ybase + (size_t)k * (COUT * TVN);
        float vals[VV];
        #pragma unroll
        for (int v = 0; v < VV; v++) vals[v] = yr[v];
        #pragma unroll
        for (int v = 0; v < VV; v++) {
            const float val = vals[v];
            #pragma unroll
            for (int w = 0; w < VV; w++) acc[w] += val * As[k][v][w];
        }
    }

    float* out = g_y + ((size_t)n * COUT + c) * TVN + tid * VV;
    float s = 0.0f, s2 = 0.0f;
    #pragma unroll
    for (int w = 0; w < VV; w++) {
        out[w] = acc[w];
        s  += acc[w];
        s2 += acc[w] * acc[w];
    }

    // Block reduce then atomics
    #pragma unroll
    for (int off = 16; off > 0; off >>= 1) {
        s  += __shfl_down_sync(0xFFFFFFFFu, s,  off);
        s2 += __shfl_down_sync(0xFFFFFFFFu, s2, off);
    }
    const int lane = tid & 31, warp = tid >> 5;
    if (lane == 0) { red_s[warp] = s; red_s2[warp] = s2; }
    __syncthreads();
    if (tid == 0) {
        float S  = red_s[0]  + red_s[1]  + red_s[2]  + red_s[3];
        float S2 = red_s2[0] + red_s2[1] + red_s2[2] + red_s2[3];
        atomicAdd(&g_sum[c],   S);
        atomicAdd(&g_sqsum[c], S2);
    }
}

// ---------------------------------------------------------------------------
// Kernel 3: BN finalize + affine + ReLU (float4 elementwise)
// ---------------------------------------------------------------------------
__global__ __launch_bounds__(256) void bn_kernel(
    const float* __restrict__ gamma, const float* __restrict__ beta, float* __restrict__ out)
{
    const size_t i = (size_t)blockIdx.x * 256 + threadIdx.x;   // float4 index
    const int c = (int)((i * 4) / TVN) % COUT;                 // 4 | TVN -> uniform in vec

    const float cnt_inv = 1.0f / (float)NTV;
    const float mu  = g_sum[c] * cnt_inv;
    const float var = g_sqsum[c] * cnt_inv - mu * mu;
    const float inv = rsqrtf(var + BN_EPS);
    const float scale = gamma[c] * inv;
    const float shift = beta[c] - mu * scale;

    float4 v = ((const float4*)g_y)[i];
    v.x = fmaxf(v.x * scale + shift, 0.0f);
    v.y = fmaxf(v.y * scale + shift, 0.0f);
    v.z = fmaxf(v.z * scale + shift, 0.0f);
    v.w = fmaxf(v.w * scale + shift, 0.0f);
    ((float4*)out)[i] = v;
}

// ---------------------------------------------------------------------------
extern "C" void kernel_launch(void* const* d_in, const int* in_sizes, int n_in,
                              void* d_out, int out_size)
{
    const float* x     = (const float*)d_in[0];   // [32,256,128,25]
    const float* A     = (const float*)d_in[1];   // [3,25,25]
    const float* W     = (const float*)d_in[2];   // [768,256]
    const float* b     = (const float*)d_in[3];   // [768]
    const float* gamma = (const float*)d_in[4];   // [256]
    const float* beta  = (const float*)d_in[5];   // [256]

    zero_stats_kernel<<<1, 256>>>();

    dim3 g1(6, 800);
    gemm_kernel<<<g1, 256>>>(x, W, b);

    dim3 g2(COUT, NB);
    contract_kernel<<<g2, 128>>>(A);

    const int nvec = (NB * COUT * TVN) / 4;       // 6,553,600
    bn_kernel<<<nvec / 256, 256>>>(gamma, beta, (float*)d_out);
}

// round 5
// speedup vs baseline: 1.8609x; 1.2015x over previous
#include <cuda_runtime.h>
#include <cuda_bf16.h>
#include <cstdint>

// Problem constants
#define NB    32
#define CIN   256
#define COUT  256
#define TT    128
#define VV    25
#define KK    3
#define KCOUT 768
#define TVN   3200         // T*V
#define NTV   102400       // N*T*V
#define BN_EPS 1e-5f

#define NSLOT 16           // BN-stat contention slots

// Device-global scratch (allocation-free per harness rules)
__device__ float g_y   [(size_t)NB * COUT * TVN];   // fused output pre-BN, 105 MB
__device__ float g_Wtf [KCOUT * CIN];               // reordered + tf32-rna W
__device__ float g_sum2[NSLOT * COUT];
__device__ float g_sq2 [NSLOT * COUT];
__device__ float g_scale[COUT];
__device__ float g_shift[COUT];

// ---------------------------------------------------------------------------
__device__ __forceinline__ uint32_t f2tf(float f) {
    uint32_t r;
    asm("cvt.rna.tf32.f32 %0, %1;" : "=r"(r) : "f"(f));
    return r;
}

__device__ __forceinline__ void mma_tf32(float c[4], const uint32_t a[4], uint32_t b0, uint32_t b1) {
    asm volatile(
        "mma.sync.aligned.m16n8k8.row.col.f32.tf32.tf32.f32 "
        "{%0,%1,%2,%3}, {%4,%5,%6,%7}, {%8,%9}, {%0,%1,%2,%3};\n"
        : "+f"(c[0]), "+f"(c[1]), "+f"(c[2]), "+f"(c[3])
        : "r"(a[0]), "r"(a[1]), "r"(a[2]), "r"(a[3]), "r"(b0), "r"(b1));
}

__device__ __forceinline__ uint32_t smem_u32(const void* p) {
    return (uint32_t)__cvta_generic_to_shared(p);
}
__device__ __forceinline__ void cp16(uint32_t dst, const void* src) {
    asm volatile("cp.async.cg.shared.global [%0], [%1], 16;" :: "r"(dst), "l"(src));
}

// ---------------------------------------------------------------------------
// Kernel A: zero BN slot accumulators
__global__ void zero_stats_kernel() {
    int i = blockIdx.x * 256 + threadIdx.x;
    if (i < NSLOT * COUT) { g_sum2[i] = 0.0f; g_sq2[i] = 0.0f; }
}

// Kernel B: reorder W rows to o' = c*3 + k and convert to tf32 (rna)
__global__ void convW_kernel(const float* __restrict__ W) {
    int op = blockIdx.x;          // 0..767
    int ci = threadIdx.x;         // 0..255
    int c = op / 3, k = op % 3;
    g_Wtf[op * CIN + ci] = __uint_as_float(f2tf(W[(k * COUT + c) * CIN + ci]));
}

// ---------------------------------------------------------------------------
// Kernel C: fused  y[n,c,t,w] = sum_{k,v}( (W x)[n,kc,t,v] + b ) * A[k,v,w]
//   GEMM: M=96 (32c x 3k interleaved), N=200 (8 t), K=256, kstep=32,
//   3-stage cp.async pipeline.  Epilogue: tensor-core v->w contraction,
//   BN partial stats, coalesced store of y.
// ---------------------------------------------------------------------------
#define LDA 36      // smem stride for W tile (96 x 32)
#define LDB 200     // smem stride for x tile (32 x 200)
#define A_STG (96 * LDA)     // 3456 floats / stage
#define B_STG (32 * LDB)     // 6400 floats / stage
#define NSTEP 8

#define Y1S_FL (96 * 200 + 64)   // y1 tile + overflow pad
#define DYN_FL (3 * A_STG + 3 * B_STG)   // 29568 floats = 118272 B (>= epi use)

__global__ __launch_bounds__(256, 1) void fused_kernel(
    const float* __restrict__ x, const float* __restrict__ A,
    const float* __restrict__ bias)
{
    extern __shared__ float dyn[];
    float* AsB = dyn;                 // [3][96*36]
    float* BsB = dyn + 3 * A_STG;     // [3][32*200]
    float* y1s = dyn;                 // epilogue alias, 96*200 (+pad)
    float* y2s = dyn + Y1S_FL;        // 32*200

    __shared__ uint32_t Apu[KK][32][32];   // zero-padded tf32 adjacency
    __shared__ float biass[96];

    const int tid  = threadIdx.x;
    const int lane = tid & 31;
    const int warp = tid >> 5;
    const int wm   = warp >> 2;      // 0..1  (M half: 48 rows)
    const int wn   = warp & 3;       // 0..3  (N group, n-tiles j = wn+4i)
    const int g    = lane >> 2;
    const int k4   = lane & 3;

    const int m0   = blockIdx.x * 96;       // 8 M tiles
    const int c0   = blockIdx.x * 32;
    const int ct   = blockIdx.y;            // 512 column tiles
    const int n    = ct >> 4;
    const int tvbase = (ct & 15) * 200;
    const int slot = ct & (NSLOT - 1);

    const float* xB = x + (size_t)n * (CIN * TVN) + tvbase;

    // --- one-pass fills of static smem (consumed only after later syncs) ---
    for (int i = tid; i < KK * 32 * 32; i += 256) {
        int k = i >> 10, v = (i >> 5) & 31, w = i & 31;
        ((uint32_t*)Apu)[i] = (v < VV && w < VV) ? f2tf(A[(k * VV + v) * VV + w]) : 0u;
    }
    if (tid < 96) {
        int op = m0 + tid;
        biass[tid] = bias[(op % 3) * COUT + (op / 3)];
    }

    float acc[3][7][4];
    #pragma unroll
    for (int mi = 0; mi < 3; mi++)
        #pragma unroll
        for (int i = 0; i < 7; i++)
            #pragma unroll
            for (int r = 0; r < 4; r++) acc[mi][i][r] = 0.0f;

    // ---- pipeline issue helper ----
    auto issue = [&](int s) {
        const int kk  = s * 32;
        const int buf = s % 3;
        float* Asb = AsB + buf * A_STG;
        float* Bsb = BsB + buf * B_STG;
        #pragma unroll
        for (int p = 0; p < 3; p++) {              // 768 float4 of W tile
            int i = tid + p * 256;
            int row = i >> 3, c4 = (i & 7) * 4;
            cp16(smem_u32(Asb + row * LDA + c4),
                 g_Wtf + (size_t)(m0 + row) * CIN + kk + c4);
        }
        #pragma unroll
        for (int p = 0; p < 7; p++) {              // 1600 float4 of x tile
            int i = tid + p * 256;
            if (i < 1600) {
                int row = i / 50, c4 = (i % 50) * 4;
                cp16(smem_u32(Bsb + row * LDB + c4),
                     xB + (size_t)(kk + row) * TVN + c4);
            }
        }
        asm volatile("cp.async.commit_group;");
    };

    issue(0);
    issue(1);

    for (int s = 0; s < NSTEP; s++) {
        if (s < NSTEP - 1) asm volatile("cp.async.wait_group 1;" ::: "memory");
        else               asm volatile("cp.async.wait_group 0;" ::: "memory");
        __syncthreads();
        if (s + 2 < NSTEP) issue(s + 2);

        const int buf = s % 3;
        const uint32_t* Asb = (const uint32_t*)(AsB + buf * A_STG);
        const uint32_t* Bsb = (const uint32_t*)(BsB + buf * B_STG);

        #pragma unroll
        for (int k8 = 0; k8 < 4; k8++) {
            uint32_t a[3][4], b[7][2];
            #pragma unroll
            for (int mi = 0; mi < 3; mi++) {
                const uint32_t* base = &Asb[(wm * 48 + mi * 16 + g) * LDA + k8 * 8 + k4];
                a[mi][0] = base[0];
                a[mi][1] = base[8 * LDA];
                a[mi][2] = base[4];
                a[mi][3] = base[8 * LDA + 4];
            }
            #pragma unroll
            for (int i = 0; i < 7; i++) {
                int j = wn + 4 * i;
                if (j < 25) {
                    const uint32_t* base = &Bsb[(k8 * 8 + k4) * LDB + j * 8 + g];
                    b[i][0] = base[0];
                    b[i][1] = base[4 * LDB];
                }
            }
            #pragma unroll
            for (int mi = 0; mi < 3; mi++)
                #pragma unroll
                for (int i = 0; i < 7; i++)
                    if (wn + 4 * i < 25) mma_tf32(acc[mi][i], a[mi], b[i][0], b[i][1]);
        }
    }

    // ---------------- epilogue ----------------
    __syncthreads();   // all mainloop smem reads complete; safe to alias

    // 1) accs (+bias) -> y1s tile [96][200]
    #pragma unroll
    for (int mi = 0; mi < 3; mi++) {
        #pragma unroll
        for (int h = 0; h < 2; h++) {
            const int row = wm * 48 + mi * 16 + h * 8 + g;
            const float bv = biass[row];
            #pragma unroll
            for (int i = 0; i < 7; i++) {
                int j = wn + 4 * i;
                if (j < 25) {
                    float2 v;
                    v.x = acc[mi][i][h * 2 + 0] + bv;
                    v.y = acc[mi][i][h * 2 + 1] + bv;
                    *(float2*)&y1s[row * 200 + j * 8 + k4 * 2] = v;
                }
            }
        }
    }
    __syncthreads();

    // 2) per-warp (t = warp) contraction via mma: [32c x 25v] @ Apad[32v x 32w]
    const int t = warp;
    const uint32_t* y1u = (const uint32_t*)y1s;
    float acc2[2][4][4];
    #pragma unroll
    for (int mi = 0; mi < 2; mi++)
        #pragma unroll
        for (int nj = 0; nj < 4; nj++)
            #pragma unroll
            for (int r = 0; r < 4; r++) acc2[mi][nj][r] = 0.0f;

    #pragma unroll
    for (int kk3 = 0; kk3 < KK; kk3++) {
        #pragma unroll
        for (int k8 = 0; k8 < 4; k8++) {
            uint32_t a[2][4], b[4][2];
            #pragma unroll
            for (int mi = 0; mi < 2; mi++) {
                const int c = mi * 16 + g;
                const int base = (3 * c + kk3) * 200 + t * 25 + k8 * 8 + k4;
                a[mi][0] = y1u[base];
                a[mi][1] = y1u[base + 24 * 200];   // row c+8 -> +24 y1s rows
                a[mi][2] = y1u[base + 4];
                a[mi][3] = y1u[base + 24 * 200 + 4];
            }
            #pragma unroll
            for (int nj = 0; nj < 4; nj++) {
                b[nj][0] = Apu[kk3][k8 * 8 + k4][nj * 8 + g];
                b[nj][1] = Apu[kk3][k8 * 8 + k4 + 4][nj * 8 + g];
            }
            #pragma unroll
            for (int mi = 0; mi < 2; mi++)
                #pragma unroll
                for (int nj = 0; nj < 4; nj++)
                    mma_tf32(acc2[mi][nj], a[mi], b[nj][0], b[nj][1]);
        }
    }

    // 3) store contraction result -> y2s [32c][200]
    //    SCALAR stores: base offset t*25 is odd for odd t, so float2 would be
    //    misaligned (this was the R4 "misaligned address" crash).
    #pragma unroll
    for (int mi = 0; mi < 2; mi++) {
        #pragma unroll
        for (int h = 0; h < 2; h++) {
            const int c = mi * 16 + h * 8 + g;
            #pragma unroll
            for (int nj = 0; nj < 4; nj++) {
                const int wcol = nj * 8 + k4 * 2;
                if (wcol < VV)     y2s[c * 200 + t * 25 + wcol]     = acc2[mi][nj][h * 2 + 0];
                if (wcol + 1 < VV) y2s[c * 200 + t * 25 + wcol + 1] = acc2[mi][nj][h * 2 + 1];
            }
        }
    }
    __syncthreads();

    // 4) BN partial stats: thread = (c_local, t_local)
    {
        const int cl = tid >> 3, tl = tid & 7;
        float s = 0.0f, s2 = 0.0f;
        #pragma unroll
        for (int v = 0; v < VV; v++) {
            float val = y2s[cl * 200 + tl * 25 + v];
            s += val; s2 += val * val;
        }
        s  += __shfl_down_sync(0xFFFFFFFFu, s,  4, 8);
        s2 += __shfl_down_sync(0xFFFFFFFFu, s2, 4, 8);
        s  += __shfl_down_sync(0xFFFFFFFFu, s,  2, 8);
        s2 += __shfl_down_sync(0xFFFFFFFFu, s2, 2, 8);
        s  += __shfl_down_sync(0xFFFFFFFFu, s,  1, 8);
        s2 += __shfl_down_sync(0xFFFFFFFFu, s2, 1, 8);
        if ((tid & 7) == 0) {
            atomicAdd(&g_sum2[slot * COUT + c0 + cl], s);
            atomicAdd(&g_sq2 [slot * COUT + c0 + cl], s2);
        }
    }

    // 5) coalesced copy y2s -> g_y
    float* ydst = g_y + ((size_t)n * COUT + c0) * TVN + tvbase;
    #pragma unroll
    for (int p = 0; p < 7; p++) {
        int i = tid + p * 256;
        if (i < 1600) {
            int row = i / 50, c4 = (i % 50) * 4;
            float4 v = *(float4*)&y2s[row * 200 + c4];
            *(float4*)(ydst + (size_t)row * TVN + c4) = v;
        }
    }
}

// ---------------------------------------------------------------------------
// Kernel D: finalize per-channel BN scale/shift (1 block)
__global__ void finalize_kernel(const float* __restrict__ gamma, const float* __restrict__ beta) {
    int c = threadIdx.x;
    float s = 0.0f, s2 = 0.0f;
    #pragma unroll
    for (int sl = 0; sl < NSLOT; sl++) {
        s  += g_sum2[sl * COUT + c];
        s2 += g_sq2 [sl * COUT + c];
    }
    const float inv_n = 1.0f / (float)NTV;
    const float mu  = s * inv_n;
    const float var = s2 * inv_n - mu * mu;
    const float rin = rsqrtf(var + BN_EPS);
    const float sc  = gamma[c] * rin;
    g_scale[c] = sc;
    g_shift[c] = beta[c] - mu * sc;
}

// Kernel E: normalize + ReLU (pure streaming)
__global__ __launch_bounds__(256) void bn_kernel(float* __restrict__ out)
{
    const size_t i = (size_t)blockIdx.x * 256 + threadIdx.x;   // float4 index
    const int c = (int)((i * 4) / TVN) % COUT;
    const float sc = g_scale[c];
    const float sh = g_shift[c];
    float4 v = ((const float4*)g_y)[i];
    v.x = fmaxf(v.x * sc + sh, 0.0f);
    v.y = fmaxf(v.y * sc + sh, 0.0f);
    v.z = fmaxf(v.z * sc + sh, 0.0f);
    v.w = fmaxf(v.w * sc + sh, 0.0f);
    ((float4*)out)[i] = v;
}

// ---------------------------------------------------------------------------
extern "C" void kernel_launch(void* const* d_in, const int* in_sizes, int n_in,
                              void* d_out, int out_size)
{
    const float* x     = (const float*)d_in[0];   // [32,256,128,25]
    const float* A     = (const float*)d_in[1];   // [3,25,25]
    const float* W     = (const float*)d_in[2];   // [768,256]
    const float* b     = (const float*)d_in[3];   // [768]
    const float* gamma = (const float*)d_in[4];   // [256]
    const float* beta  = (const float*)d_in[5];   // [256]

    static const int DYN_BYTES = DYN_FL * 4;      // 118272
    cudaFuncSetAttribute(fused_kernel, cudaFuncAttributeMaxDynamicSharedMemorySize, DYN_BYTES);

    zero_stats_kernel<<<(NSLOT * COUT + 255) / 256, 256>>>();
    convW_kernel<<<KCOUT, CIN>>>(W);

    dim3 grid(8, 512);   // M tiles fastest -> concurrent blocks share x column tiles via L2
    fused_kernel<<<grid, 256, DYN_BYTES>>>(x, A, b);

    finalize_kernel<<<1, COUT>>>(gamma, beta);

    const int nvec = (NB * COUT * TVN) / 4;
    bn_kernel<<<nvec / 256, 256>>>((float*)d_out);
}

// round 6
// speedup vs baseline: 1.8642x; 1.0018x over previous
#include <cuda_runtime.h>
#include <cuda_bf16.h>
#include <cstdint>

// Problem constants
#define NB    32
#define CIN   256
#define COUT  256
#define TT    128
#define VV    25
#define KK    3
#define KCOUT 768
#define TVN   3200         // T*V
#define NTV   102400       // N*T*V
#define BN_EPS 1e-5f

#define NSLOT 16           // BN-stat contention slots

// Device-global scratch (allocation-free per harness rules)
__device__ float g_y   [(size_t)NB * COUT * TVN];   // fused output pre-BN, 105 MB
__device__ float g_Wtf [KCOUT * CIN];               // reordered + tf32-rna W
__device__ float g_sum2[NSLOT * COUT];
__device__ float g_sq2 [NSLOT * COUT];
__device__ float g_scale[COUT];
__device__ float g_shift[COUT];

// ---------------------------------------------------------------------------
__device__ __forceinline__ uint32_t f2tf(float f) {
    uint32_t r;
    asm("cvt.rna.tf32.f32 %0, %1;" : "=r"(r) : "f"(f));
    return r;
}

__device__ __forceinline__ void mma_tf32(float c[4], const uint32_t a[4], uint32_t b0, uint32_t b1) {
    asm volatile(
        "mma.sync.aligned.m16n8k8.row.col.f32.tf32.tf32.f32 "
        "{%0,%1,%2,%3}, {%4,%5,%6,%7}, {%8,%9}, {%0,%1,%2,%3};\n"
        : "+f"(c[0]), "+f"(c[1]), "+f"(c[2]), "+f"(c[3])
        : "r"(a[0]), "r"(a[1]), "r"(a[2]), "r"(a[3]), "r"(b0), "r"(b1));
}

__device__ __forceinline__ uint32_t smem_u32(const void* p) {
    return (uint32_t)__cvta_generic_to_shared(p);
}
__device__ __forceinline__ void cp16(uint32_t dst, const void* src) {
    asm volatile("cp.async.cg.shared.global [%0], [%1], 16;" :: "r"(dst), "l"(src));
}

// ---------------------------------------------------------------------------
// Kernel A: zero BN slot accumulators
__global__ void zero_stats_kernel() {
    int i = blockIdx.x * 256 + threadIdx.x;
    if (i < NSLOT * COUT) { g_sum2[i] = 0.0f; g_sq2[i] = 0.0f; }
}

// Kernel B: reorder W rows to o' = c*3 + k and convert to tf32 (rna)
__global__ void convW_kernel(const float* __restrict__ W) {
    int op = blockIdx.x;          // 0..767
    int ci = threadIdx.x;         // 0..255
    int c = op / 3, k = op % 3;
    g_Wtf[op * CIN + ci] = __uint_as_float(f2tf(W[(k * COUT + c) * CIN + ci]));
}

// ---------------------------------------------------------------------------
// Kernel C: fused  y[n,c,t,w] = sum_{k,v}( (W x)[n,kc,t,v] + b ) * A[k,v,w]
//   GEMM: M=96 (32c x 3k interleaved), N=200 (8 t), K=256, kstep=32,
//   3-stage cp.async pipeline.  Epilogue: tensor-core v->w contraction,
//   BN partial stats, coalesced store of y.
// ---------------------------------------------------------------------------
#define LDA 36      // smem stride for W tile (96 x 32)
#define LDB 200     // smem stride for x tile (32 x 200)
#define A_STG (96 * LDA)     // 3456 floats / stage
#define B_STG (32 * LDB)     // 6400 floats / stage
#define NSTEP 8

#define Y1S_FL (96 * 200 + 64)   // y1 tile + overflow pad
#define DYN_FL (3 * A_STG + 3 * B_STG)   // 29568 floats = 118272 B (>= epi use)

__global__ __launch_bounds__(256, 1) void fused_kernel(
    const float* __restrict__ x, const float* __restrict__ A,
    const float* __restrict__ bias)
{
    extern __shared__ float dyn[];
    float* AsB = dyn;                 // [3][96*36]
    float* BsB = dyn + 3 * A_STG;     // [3][32*200]
    float* y1s = dyn;                 // epilogue alias, 96*200 (+pad)
    float* y2s = dyn + Y1S_FL;        // 32*200

    __shared__ uint32_t Apu[KK][32][32];   // zero-padded tf32 adjacency
    __shared__ float biass[96];

    const int tid  = threadIdx.x;
    const int lane = tid & 31;
    const int warp = tid >> 5;
    const int wm   = warp >> 2;      // 0..1  (M half: 48 rows)
    const int wn   = warp & 3;       // 0..3  (N group, n-tiles j = wn+4i)
    const int g    = lane >> 2;
    const int k4   = lane & 3;

    const int m0   = blockIdx.x * 96;       // 8 M tiles
    const int c0   = blockIdx.x * 32;
    const int ct   = blockIdx.y;            // 512 column tiles
    const int n    = ct >> 4;
    const int tvbase = (ct & 15) * 200;
    const int slot = ct & (NSLOT - 1);

    const float* xB = x + (size_t)n * (CIN * TVN) + tvbase;

    // --- one-pass fills of static smem (consumed only after later syncs) ---
    for (int i = tid; i < KK * 32 * 32; i += 256) {
        int k = i >> 10, v = (i >> 5) & 31, w = i & 31;
        ((uint32_t*)Apu)[i] = (v < VV && w < VV) ? f2tf(A[(k * VV + v) * VV + w]) : 0u;
    }
    if (tid < 96) {
        int op = m0 + tid;
        biass[tid] = bias[(op % 3) * COUT + (op / 3)];
    }

    float acc[3][7][4];
    #pragma unroll
    for (int mi = 0; mi < 3; mi++)
        #pragma unroll
        for (int i = 0; i < 7; i++)
            #pragma unroll
            for (int r = 0; r < 4; r++) acc[mi][i][r] = 0.0f;

    // ---- pipeline issue helper ----
    auto issue = [&](int s) {
        const int kk  = s * 32;
        const int buf = s % 3;
        float* Asb = AsB + buf * A_STG;
        float* Bsb = BsB + buf * B_STG;
        #pragma unroll
        for (int p = 0; p < 3; p++) {              // 768 float4 of W tile
            int i = tid + p * 256;
            int row = i >> 3, c4 = (i & 7) * 4;
            cp16(smem_u32(Asb + row * LDA + c4),
                 g_Wtf + (size_t)(m0 + row) * CIN + kk + c4);
        }
        #pragma unroll
        for (int p = 0; p < 7; p++) {              // 1600 float4 of x tile
            int i = tid + p * 256;
            if (i < 1600) {
                int row = i / 50, c4 = (i % 50) * 4;
                cp16(smem_u32(Bsb + row * LDB + c4),
                     xB + (size_t)(kk + row) * TVN + c4);
            }
        }
        asm volatile("cp.async.commit_group;");
    };

    issue(0);
    issue(1);

    for (int s = 0; s < NSTEP; s++) {
        if (s < NSTEP - 1) asm volatile("cp.async.wait_group 1;" ::: "memory");
        else               asm volatile("cp.async.wait_group 0;" ::: "memory");
        __syncthreads();
        if (s + 2 < NSTEP) issue(s + 2);

        const int buf = s % 3;
        const uint32_t* Asb = (const uint32_t*)(AsB + buf * A_STG);
        const uint32_t* Bsb = (const uint32_t*)(BsB + buf * B_STG);

        #pragma unroll
        for (int k8 = 0; k8 < 4; k8++) {
            uint32_t a[3][4], b[7][2];
            #pragma unroll
            for (int mi = 0; mi < 3; mi++) {
                const uint32_t* base = &Asb[(wm * 48 + mi * 16 + g) * LDA + k8 * 8 + k4];
                a[mi][0] = base[0];
                a[mi][1] = base[8 * LDA];
                a[mi][2] = base[4];
                a[mi][3] = base[8 * LDA + 4];
            }
            #pragma unroll
            for (int i = 0; i < 7; i++) {
                int j = wn + 4 * i;
                if (j < 25) {
                    const uint32_t* base = &Bsb[(k8 * 8 + k4) * LDB + j * 8 + g];
                    b[i][0] = base[0];
                    b[i][1] = base[4 * LDB];
                }
            }
            #pragma unroll
            for (int mi = 0; mi < 3; mi++)
                #pragma unroll
                for (int i = 0; i < 7; i++)
                    if (wn + 4 * i < 25) mma_tf32(acc[mi][i], a[mi], b[i][0], b[i][1]);
        }
    }

    // ---------------- epilogue ----------------
    __syncthreads();   // all mainloop smem reads complete; safe to alias

    // 1) accs (+bias) -> y1s tile [96][200]
    #pragma unroll
    for (int mi = 0; mi < 3; mi++) {
        #pragma unroll
        for (int h = 0; h < 2; h++) {
            const int row = wm * 48 + mi * 16 + h * 8 + g;
            const float bv = biass[row];
            #pragma unroll
            for (int i = 0; i < 7; i++) {
                int j = wn + 4 * i;
                if (j < 25) {
                    float2 v;
                    v.x = acc[mi][i][h * 2 + 0] + bv;
                    v.y = acc[mi][i][h * 2 + 1] + bv;
                    *(float2*)&y1s[row * 200 + j * 8 + k4 * 2] = v;
                }
            }
        }
    }
    __syncthreads();

    // 2) per-warp (t = warp) contraction via mma: [32c x 25v] @ Apad[32v x 32w]
    const int t = warp;
    const uint32_t* y1u = (const uint32_t*)y1s;
    float acc2[2][4][4];
    #pragma unroll
    for (int mi = 0; mi < 2; mi++)
        #pragma unroll
        for (int nj = 0; nj < 4; nj++)
            #pragma unroll
            for (int r = 0; r < 4; r++) acc2[mi][nj][r] = 0.0f;

    #pragma unroll
    for (int kk3 = 0; kk3 < KK; kk3++) {
        #pragma unroll
        for (int k8 = 0; k8 < 4; k8++) {
            uint32_t a[2][4], b[4][2];
            #pragma unroll
            for (int mi = 0; mi < 2; mi++) {
                const int c = mi * 16 + g;
                const int base = (3 * c + kk3) * 200 + t * 25 + k8 * 8 + k4;
                a[mi][0] = y1u[base];
                a[mi][1] = y1u[base + 24 * 200];   // row c+8 -> +24 y1s rows
                a[mi][2] = y1u[base + 4];
                a[mi][3] = y1u[base + 24 * 200 + 4];
            }
            #pragma unroll
            for (int nj = 0; nj < 4; nj++) {
                b[nj][0] = Apu[kk3][k8 * 8 + k4][nj * 8 + g];
                b[nj][1] = Apu[kk3][k8 * 8 + k4 + 4][nj * 8 + g];
            }
            #pragma unroll
            for (int mi = 0; mi < 2; mi++)
                #pragma unroll
                for (int nj = 0; nj < 4; nj++)
                    mma_tf32(acc2[mi][nj], a[mi], b[nj][0], b[nj][1]);
        }
    }

    // 3) store contraction result -> y2s [32c][200]
    //    SCALAR stores: base offset t*25 is odd for odd t, so float2 would be
    //    misaligned (this was the R4 "misaligned address" crash).
    #pragma unroll
    for (int mi = 0; mi < 2; mi++) {
        #pragma unroll
        for (int h = 0; h < 2; h++) {
            const int c = mi * 16 + h * 8 + g;
            #pragma unroll
            for (int nj = 0; nj < 4; nj++) {
                const int wcol = nj * 8 + k4 * 2;
                if (wcol < VV)     y2s[c * 200 + t * 25 + wcol]     = acc2[mi][nj][h * 2 + 0];
                if (wcol + 1 < VV) y2s[c * 200 + t * 25 + wcol + 1] = acc2[mi][nj][h * 2 + 1];
            }
        }
    }
    __syncthreads();

    // 4) BN partial stats: thread = (c_local, t_local)
    {
        const int cl = tid >> 3, tl = tid & 7;
        float s = 0.0f, s2 = 0.0f;
        #pragma unroll
        for (int v = 0; v < VV; v++) {
            float val = y2s[cl * 200 + tl * 25 + v];
            s += val; s2 += val * val;
        }
        s  += __shfl_down_sync(0xFFFFFFFFu, s,  4, 8);
        s2 += __shfl_down_sync(0xFFFFFFFFu, s2, 4, 8);
        s  += __shfl_down_sync(0xFFFFFFFFu, s,  2, 8);
        s2 += __shfl_down_sync(0xFFFFFFFFu, s2, 2, 8);
        s  += __shfl_down_sync(0xFFFFFFFFu, s,  1, 8);
        s2 += __shfl_down_sync(0xFFFFFFFFu, s2, 1, 8);
        if ((tid & 7) == 0) {
            atomicAdd(&g_sum2[slot * COUT + c0 + cl], s);
            atomicAdd(&g_sq2 [slot * COUT + c0 + cl], s2);
        }
    }

    // 5) coalesced copy y2s -> g_y
    float* ydst = g_y + ((size_t)n * COUT + c0) * TVN + tvbase;
    #pragma unroll
    for (int p = 0; p < 7; p++) {
        int i = tid + p * 256;
        if (i < 1600) {
            int row = i / 50, c4 = (i % 50) * 4;
            float4 v = *(float4*)&y2s[row * 200 + c4];
            *(float4*)(ydst + (size_t)row * TVN + c4) = v;
        }
    }
}

// ---------------------------------------------------------------------------
// Kernel D: finalize per-channel BN scale/shift (1 block)
__global__ void finalize_kernel(const float* __restrict__ gamma, const float* __restrict__ beta) {
    int c = threadIdx.x;
    float s = 0.0f, s2 = 0.0f;
    #pragma unroll
    for (int sl = 0; sl < NSLOT; sl++) {
        s  += g_sum2[sl * COUT + c];
        s2 += g_sq2 [sl * COUT + c];
    }
    const float inv_n = 1.0f / (float)NTV;
    const float mu  = s * inv_n;
    const float var = s2 * inv_n - mu * mu;
    const float rin = rsqrtf(var + BN_EPS);
    const float sc  = gamma[c] * rin;
    g_scale[c] = sc;
    g_shift[c] = beta[c] - mu * sc;
}

// Kernel E: normalize + ReLU (pure streaming)
__global__ __launch_bounds__(256) void bn_kernel(float* __restrict__ out)
{
    const size_t i = (size_t)blockIdx.x * 256 + threadIdx.x;   // float4 index
    const int c = (int)((i * 4) / TVN) % COUT;
    const float sc = g_scale[c];
    const float sh = g_shift[c];
    float4 v = ((const float4*)g_y)[i];
    v.x = fmaxf(v.x * sc + sh, 0.0f);
    v.y = fmaxf(v.y * sc + sh, 0.0f);
    v.z = fmaxf(v.z * sc + sh, 0.0f);
    v.w = fmaxf(v.w * sc + sh, 0.0f);
    ((float4*)out)[i] = v;
}

// ---------------------------------------------------------------------------
extern "C" void kernel_launch(void* const* d_in, const int* in_sizes, int n_in,
                              void* d_out, int out_size)
{
    const float* x     = (const float*)d_in[0];   // [32,256,128,25]
    const float* A     = (const float*)d_in[1];   // [3,25,25]
    const float* W     = (const float*)d_in[2];   // [768,256]
    const float* b     = (const float*)d_in[3];   // [768]
    const float* gamma = (const float*)d_in[4];   // [256]
    const float* beta  = (const float*)d_in[5];   // [256]

    static const int DYN_BYTES = DYN_FL * 4;      // 118272
    cudaFuncSetAttribute(fused_kernel, cudaFuncAttributeMaxDynamicSharedMemorySize, DYN_BYTES);

    zero_stats_kernel<<<(NSLOT * COUT + 255) / 256, 256>>>();
    convW_kernel<<<KCOUT, CIN>>>(W);

    dim3 grid(8, 512);   // M tiles fastest -> concurrent blocks share x column tiles via L2
    fused_kernel<<<grid, 256, DYN_BYTES>>>(x, A, b);

    finalize_kernel<<<1, COUT>>>(gamma, beta);

    const int nvec = (NB * COUT * TVN) / 4;
    bn_kernel<<<nvec / 256, 256>>>((float*)d_out);
}

// round 8
// speedup vs baseline: 2.4440x; 1.3110x over previous
#include <cuda_runtime.h>
#include <cuda_fp16.h>
#include <cstdint>

// Problem constants
#define NB    32
#define CIN   256
#define COUT  256
#define TT    128
#define VV    25
#define KK    3
#define KCOUT 768
#define TVN   3200         // T*V
#define NTV   102400       // N*T*V
#define BN_EPS 1e-5f
#define NSLOT 16

// Device-global scratch (allocation-free per harness rules)
__device__ float  g_y [(size_t)NB * COUT * TVN];    // pre-BN output, 105 MB
__device__ __half g_Wh[KCOUT * CIN];                // fp16 W, rows o' = c*3+k
__device__ __half g_xh[(size_t)NB * TVN * CIN];     // fp16 x transposed [n][tv][ci], 52 MB
__device__ float  g_sum2[NSLOT * COUT];
__device__ float  g_sq2 [NSLOT * COUT];
__device__ float  g_scale[COUT];
__device__ float  g_shift[COUT];

// ---------------------------------------------------------------------------
__device__ __forceinline__ uint32_t f2tf(float f) {
    uint32_t r;
    asm("cvt.rna.tf32.f32 %0, %1;" : "=r"(r) : "f"(f));
    return r;
}
__device__ __forceinline__ uint32_t smem_u32(const void* p) {
    return (uint32_t)__cvta_generic_to_shared(p);
}
__device__ __forceinline__ void cp16(uint32_t dst, const void* src) {
    asm volatile("cp.async.cg.shared.global [%0], [%1], 16;" :: "r"(dst), "l"(src));
}
__device__ __forceinline__ void ldsm_x4(uint32_t& r0, uint32_t& r1, uint32_t& r2, uint32_t& r3,
                                        uint32_t addr) {
    asm volatile("ldmatrix.sync.aligned.m8n8.x4.shared.b16 {%0,%1,%2,%3}, [%4];"
                 : "=r"(r0), "=r"(r1), "=r"(r2), "=r"(r3) : "r"(addr));
}
// fp16 mma, fp32 accumulate
__device__ __forceinline__ void mma_f16(float c[4], const uint32_t a[4], uint32_t b0, uint32_t b1) {
    asm volatile(
        "mma.sync.aligned.m16n8k16.row.col.f32.f16.f16.f32 "
        "{%0,%1,%2,%3}, {%4,%5,%6,%7}, {%8,%9}, {%0,%1,%2,%3};\n"
        : "+f"(c[0]), "+f"(c[1]), "+f"(c[2]), "+f"(c[3])
        : "r"(a[0]), "r"(a[1]), "r"(a[2]), "r"(a[3]), "r"(b0), "r"(b1));
}
// tf32 mma (epilogue contraction only — proven R5 path)
__device__ __forceinline__ void mma_tf32(float c[4], const uint32_t a[4], uint32_t b0, uint32_t b1) {
    asm volatile(
        "mma.sync.aligned.m16n8k8.row.col.f32.tf32.tf32.f32 "
        "{%0,%1,%2,%3}, {%4,%5,%6,%7}, {%8,%9}, {%0,%1,%2,%3};\n"
        : "+f"(c[0]), "+f"(c[1]), "+f"(c[2]), "+f"(c[3])
        : "r"(a[0]), "r"(a[1]), "r"(a[2]), "r"(a[3]), "r"(b0), "r"(b1));
}

// ---------------------------------------------------------------------------
// Prep kernels
// ---------------------------------------------------------------------------
__global__ void zero_stats_kernel() {
    int i = blockIdx.x * 256 + threadIdx.x;
    if (i < NSLOT * COUT) { g_sum2[i] = 0.0f; g_sq2[i] = 0.0f; }
}

// W[(k*256+c)*256+ci] -> g_Wh[(c*3+k)*256+ci] fp16
__global__ void convW_kernel(const float* __restrict__ W) {
    int op = blockIdx.x;          // 0..767 = c*3+k
    int ci = threadIdx.x;
    int c = op / 3, k = op % 3;
    g_Wh[op * CIN + ci] = __float2half(W[(k * COUT + c) * CIN + ci]);
}

// x[n][ci][tv] fp32 -> g_xh[n][tv][ci] fp16
__global__ __launch_bounds__(256) void transpose_kernel(const float* __restrict__ x) {
    __shared__ float tile[64][33];
    const int tv0 = blockIdx.x * 32;     // 100
    const int ci0 = blockIdx.y * 64;     // 4
    const int n   = blockIdx.z;          // 32
    const int tid = threadIdx.x;
    {
        const int tvl = tid & 31, cl = tid >> 5;   // (32, 8)
        const float* xs = x + (size_t)n * CIN * TVN + tv0 + tvl;
        #pragma unroll
        for (int it = 0; it < 8; it++) {
            int ci = cl + 8 * it;
            tile[ci][tvl] = xs[(size_t)(ci0 + ci) * TVN];
        }
    }
    __syncthreads();
    {
        const int cil = tid & 63, tl = tid >> 6;   // (64, 4)
        __half* od = g_xh + ((size_t)n * TVN + tv0) * CIN + ci0 + cil;
        #pragma unroll
        for (int it = 0; it < 8; it++) {
            int tv = tl + 4 * it;
            od[(size_t)tv * CIN] = __float2half(tile[cil][tv]);
        }
    }
}

// ---------------------------------------------------------------------------
// Fused kernel: fp16 ldmatrix/mma mainloop (M=96, N=200, K=256, kstep=64,
// 3-stage cp.async) + R5 epilogue (tf32 v->w contraction, BN stats, store).
// ---------------------------------------------------------------------------
#define STGA 12288               // 96 rows x 128 B
#define STGB 25600               // 200 rows x 128 B
#define STG  (STGA + STGB)       // 37888 B / stage
#define DYN_BYTES (3 * STG)      // 113664 B
#define Y1S_FL (96 * 200 + 64)   // fp32 y1 tile + overflow pad (epilogue alias)

__global__ __launch_bounds__(256, 1) void fused_kernel(
    const float* __restrict__ A, const float* __restrict__ bias)
{
    extern __shared__ __align__(16) char dyn[];
    const uint32_t sbu = smem_u32(dyn);
    float* y1s = (float*)dyn;                 // epilogue alias
    float* y2s = (float*)dyn + Y1S_FL;

    __shared__ uint32_t Apu[KK][32][32];      // zero-padded tf32 adjacency
    __shared__ float biass[96];

    const int tid  = threadIdx.x;
    const int lane = tid & 31;
    const int warp = tid >> 5;
    const int wm   = warp >> 2;      // 0..1  (48 M-rows each)
    const int wn   = warp & 3;       // 0..3
    const int g    = lane >> 2;
    const int k4   = lane & 3;
    const int la7  = lane & 7;
    const int la8  = (lane >> 3) & 1;
    const int la16 = (lane >> 4) & 1;
    const int q    = lane >> 3;

    const int m0     = blockIdx.x * 96;      // 8 M tiles
    const int c0     = blockIdx.x * 32;
    const int ct     = blockIdx.y;           // 512 column tiles
    const int n      = ct >> 4;
    const int tvbase = (ct & 15) * 200;
    const int slot   = ct & (NSLOT - 1);

    // static smem fills (consumed after later syncs)
    for (int i = tid; i < KK * 32 * 32; i += 256) {
        int k = i >> 10, v = (i >> 5) & 31, w = i & 31;
        ((uint32_t*)Apu)[i] = (v < VV && w < VV) ? f2tf(A[(k * VV + v) * VV + w]) : 0u;
    }
    if (tid < 96) {
        int op = m0 + tid;
        biass[tid] = bias[(op % 3) * COUT + (op / 3)];
    }

    float acc[3][7][4];
    #pragma unroll
    for (int mi = 0; mi < 3; mi++)
        #pragma unroll
        for (int i = 0; i < 7; i++)
            #pragma unroll
            for (int r = 0; r < 4; r++) acc[mi][i][r] = 0.0f;

    // ---- stage loader: A tile 96x64 fp16, B tile 200x64 fp16, SW128 rows ----
    auto issue = [&](int s) {
        const int kk = s * 64;
        const uint32_t stb = sbu + (uint32_t)(s % 3) * STG;
        #pragma unroll
        for (int p = 0; p < 3; p++) {              // 768 chunks of W tile
            int i = tid + p * 256;
            int row = i >> 3, ch = i & 7;
            uint32_t dst = stb + row * 128 + (uint32_t)((ch ^ (row & 7)) << 4);
            cp16(dst, g_Wh + (size_t)(m0 + row) * CIN + kk + ch * 8);
        }
        #pragma unroll
        for (int p = 0; p < 7; p++) {              // 1600 chunks of x tile
            int i = tid + p * 256;
            if (i < 1600) {
                int row = i >> 3, ch = i & 7;
                uint32_t dst = stb + STGA + row * 128 + (uint32_t)((ch ^ (row & 7)) << 4);
                cp16(dst, g_xh + ((size_t)n * TVN + tvbase + row) * CIN + kk + ch * 8);
            }
        }
        asm volatile("cp.async.commit_group;" ::: "memory");
    };

    issue(0);
    issue(1);

    for (int s = 0; s < 4; s++) {
        if (s < 3) asm volatile("cp.async.wait_group 1;" ::: "memory");
        else       asm volatile("cp.async.wait_group 0;" ::: "memory");
        __syncthreads();
        if (s + 2 < 4) issue(s + 2);

        const uint32_t Asb = sbu + (uint32_t)(s % 3) * STG;
        const uint32_t Bsb = Asb + STGA;

        #pragma unroll
        for (int kk16 = 0; kk16 < 4; kk16++) {
            uint32_t a[3][4], b[8][2];
            #pragma unroll
            for (int mi = 0; mi < 3; mi++) {
                int row = wm * 48 + mi * 16 + la7 + la8 * 8;
                int ch  = (kk16 * 2 + la16) ^ (row & 7);
                ldsm_x4(a[mi][0], a[mi][1], a[mi][2], a[mi][3],
                        Asb + row * 128 + (ch << 4));
            }
            #pragma unroll
            for (int p4 = 0; p4 < 4; p4++) {
                int jq = (q < 2) ? (wn + 8 * p4) : (wn + 8 * p4 + 4);
                if (jq > 24) jq = 24;                  // clamp (results unused)
                int row = jq * 8 + la7;
                int ch  = (kk16 * 2 + (q & 1)) ^ (row & 7);
                uint32_t r0, r1, r2, r3;
                ldsm_x4(r0, r1, r2, r3, Bsb + row * 128 + (ch << 4));
                b[2 * p4][0] = r0; b[2 * p4][1] = r1;
                b[2 * p4 + 1][0] = r2; b[2 * p4 + 1][1] = r3;
            }
            #pragma unroll
            for (int mi = 0; mi < 3; mi++)
                #pragma unroll
                for (int i = 0; i < 7; i++)
                    if (wn + 4 * i < 25) mma_f16(acc[mi][i], a[mi], b[i][0], b[i][1]);
        }
    }

    // ---------------- epilogue (identical to R5 passing kernel) ----------------
    __syncthreads();   // all mainloop smem reads complete; safe to alias

    // 1) accs (+bias) -> y1s fp32 tile [96][200]
    #pragma unroll
    for (int mi = 0; mi < 3; mi++) {
        #pragma unroll
        for (int h = 0; h < 2; h++) {
            const int row = wm * 48 + mi * 16 + h * 8 + g;
            const float bv = biass[row];
            #pragma unroll
            for (int i = 0; i < 7; i++) {
                int j = wn + 4 * i;
                if (j < 25) {
                    float2 v;
                    v.x = acc[mi][i][h * 2 + 0] + bv;
                    v.y = acc[mi][i][h * 2 + 1] + bv;
                    *(float2*)&y1s[row * 200 + j * 8 + k4 * 2] = v;
                }
            }
        }
    }
    __syncthreads();

    // 2) per-warp (t = warp) tf32 contraction: [32c x 25v] @ Apad[32v x 32w]
    const int t = warp;
    const uint32_t* y1u = (const uint32_t*)y1s;
    float acc2[2][4][4];
    #pragma unroll
    for (int mi = 0; mi < 2; mi++)
        #pragma unroll
        for (int nj = 0; nj < 4; nj++)
            #pragma unroll
            for (int r = 0; r < 4; r++) acc2[mi][nj][r] = 0.0f;

    #pragma unroll
    for (int kk3 = 0; kk3 < KK; kk3++) {
        #pragma unroll
        for (int k8 = 0; k8 < 4; k8++) {
            uint32_t a[2][4], b[4][2];
            #pragma unroll
            for (int mi = 0; mi < 2; mi++) {
                const int c = mi * 16 + g;
                const int base = (3 * c + kk3) * 200 + t * 25 + k8 * 8 + k4;
                a[mi][0] = y1u[base];
                a[mi][1] = y1u[base + 24 * 200];
                a[mi][2] = y1u[base + 4];
                a[mi][3] = y1u[base + 24 * 200 + 4];
            }
            #pragma unroll
            for (int nj = 0; nj < 4; nj++) {
                b[nj][0] = Apu[kk3][k8 * 8 + k4][nj * 8 + g];
                b[nj][1] = Apu[kk3][k8 * 8 + k4 + 4][nj * 8 + g];
            }
            #pragma unroll
            for (int mi = 0; mi < 2; mi++)
                #pragma unroll
                for (int nj = 0; nj < 4; nj++)
                    mma_tf32(acc2[mi][nj], a[mi], b[nj][0], b[nj][1]);
        }
    }

    // 3) store contraction result -> y2s [32c][200] (scalar: t*25 odd-offset safe)
    #pragma unroll
    for (int mi = 0; mi < 2; mi++) {
        #pragma unroll
        for (int h = 0; h < 2; h++) {
            const int c = mi * 16 + h * 8 + g;
            #pragma unroll
            for (int nj = 0; nj < 4; nj++) {
                const int wcol = nj * 8 + k4 * 2;
                if (wcol < VV)     y2s[c * 200 + t * 25 + wcol]     = acc2[mi][nj][h * 2 + 0];
                if (wcol + 1 < VV) y2s[c * 200 + t * 25 + wcol + 1] = acc2[mi][nj][h * 2 + 1];
            }
        }
    }
    __syncthreads();

    // 4) BN partial stats
    {
        const int cl = tid >> 3, tl = tid & 7;
        float s = 0.0f, s2 = 0.0f;
        #pragma unroll
        for (int v = 0; v < VV; v++) {
            float val = y2s[cl * 200 + tl * 25 + v];
            s += val; s2 += val * val;
        }
        s  += __shfl_down_sync(0xFFFFFFFFu, s,  4, 8);
        s2 += __shfl_down_sync(0xFFFFFFFFu, s2, 4, 8);
        s  += __shfl_down_sync(0xFFFFFFFFu, s,  2, 8);
        s2 += __shfl_down_sync(0xFFFFFFFFu, s2, 2, 8);
        s  += __shfl_down_sync(0xFFFFFFFFu, s,  1, 8);
        s2 += __shfl_down_sync(0xFFFFFFFFu, s2, 1, 8);
        if ((tid & 7) == 0) {
            atomicAdd(&g_sum2[slot * COUT + c0 + cl], s);
            atomicAdd(&g_sq2 [slot * COUT + c0 + cl], s2);
        }
    }

    // 5) coalesced copy y2s -> g_y
    float* ydst = g_y + ((size_t)n * COUT + c0) * TVN + tvbase;
    #pragma unroll
    for (int p = 0; p < 7; p++) {
        int i = tid + p * 256;
        if (i < 1600) {
            int row = i / 50, c4 = (i % 50) * 4;
            float4 v = *(float4*)&y2s[row * 200 + c4];
            *(float4*)(ydst + (size_t)row * TVN + c4) = v;
        }
    }
}

// ---------------------------------------------------------------------------
__global__ void finalize_kernel(const float* __restrict__ gamma, const float* __restrict__ beta) {
    int c = threadIdx.x;
    float s = 0.0f, s2 = 0.0f;
    #pragma unroll
    for (int sl = 0; sl < NSLOT; sl++) {
        s  += g_sum2[sl * COUT + c];
        s2 += g_sq2 [sl * COUT + c];
    }
    const float inv_n = 1.0f / (float)NTV;
    const float mu  = s * inv_n;
    const float var = s2 * inv_n - mu * mu;
    const float rin = rsqrtf(var + BN_EPS);
    const float sc  = gamma[c] * rin;
    g_scale[c] = sc;
    g_shift[c] = beta[c] - mu * sc;
}

__global__ __launch_bounds__(256) void bn_kernel(float* __restrict__ out)
{
    const size_t i = (size_t)blockIdx.x * 256 + threadIdx.x;
    const int c = (int)((i * 4) / TVN) % COUT;
    const float sc = g_scale[c];
    const float sh = g_shift[c];
    float4 v = ((const float4*)g_y)[i];
    v.x = fmaxf(v.x * sc + sh, 0.0f);
    v.y = fmaxf(v.y * sc + sh, 0.0f);
    v.z = fmaxf(v.z * sc + sh, 0.0f);
    v.w = fmaxf(v.w * sc + sh, 0.0f);
    ((float4*)out)[i] = v;
}

// ---------------------------------------------------------------------------
extern "C" void kernel_launch(void* const* d_in, const int* in_sizes, int n_in,
                              void* d_out, int out_size)
{
    const float* x     = (const float*)d_in[0];   // [32,256,128,25]
    const float* A     = (const float*)d_in[1];   // [3,25,25]
    const float* W     = (const float*)d_in[2];   // [768,256]
    const float* b     = (const float*)d_in[3];   // [768]
    const float* gamma = (const float*)d_in[4];   // [256]
    const float* beta  = (const float*)d_in[5];   // [256]

    cudaFuncSetAttribute(fused_kernel, cudaFuncAttributeMaxDynamicSharedMemorySize, DYN_BYTES);

    zero_stats_kernel<<<(NSLOT * COUT + 255) / 256, 256>>>();
    convW_kernel<<<KCOUT, CIN>>>(W);

    dim3 tg(100, 4, 32);
    transpose_kernel<<<tg, 256>>>(x);

    dim3 grid(8, 512);   // M tiles fastest -> blocks sharing x tiles run adjacently
    fused_kernel<<<grid, 256, DYN_BYTES>>>(A, b);

    finalize_kernel<<<1, COUT>>>(gamma, beta);

    const int nvec = (NB * COUT * TVN) / 4;
    bn_kernel<<<nvec / 256, 256>>>((float*)d_out);
}